// round 8
// baseline (speedup 1.0000x reference)
#include <cuda_runtime.h>
#include <cstdint>

// out[b, 0:128]   = emb[idx[b], :]    (128 f32)
// out[b, 128:146] = genre[idx[b], :]  (18 f32)
// idx is int32 (JAX downcasts int64 without x64).
//
// Warp handles 8 consecutive rows: two int4 idx broadcasts -> 8 independent
// float4 emb gathers + 8 predicated genre gathers, ALL issued before any
// store (MLP ~= 17 outstanding loads/warp) to hide the ~20% of gathers that
// miss L2 to DRAM (577+ cyc).
// Output stores: __stcs float2 directly from registers (row stride 584 B is
// 8B-aligned; warp's 8-row 4672 B region fully coalesced; evict-first keeps
// the 612 MB write stream from churning the L2-resident tables).

#define ROWS_PER_WARP 8

__global__ void __launch_bounds__(256)
item_gather_concat_kernel(const int*    __restrict__ idx,
                          const float4* __restrict__ emb,   // [N, 32] float4
                          const float2* __restrict__ gen,   // [N, 9]  float2
                          float2*       __restrict__ out,   // [B, 73] float2
                          int B)
{
    const int lane  = threadIdx.x & 31;
    const int gwarp = (int)((blockIdx.x * (unsigned)blockDim.x + threadIdx.x) >> 5);
    const int r0    = gwarp * ROWS_PER_WARP;

    if (r0 + ROWS_PER_WARP <= B) {
        int4 iv0 = __ldcs((const int4*)(idx + r0));       // read-once broadcasts
        int4 iv1 = __ldcs((const int4*)(idx + r0 + 4));
        int items[8] = {iv0.x, iv0.y, iv0.z, iv0.w,
                        iv1.x, iv1.y, iv1.z, iv1.w};

        // Issue all independent gathers first (max MLP), then store.
        float4 e[8];
        float2 g[8];
        #pragma unroll
        for (int j = 0; j < 8; j++)
            e[j] = __ldg(&emb[(size_t)items[j] * 32 + lane]);
        #pragma unroll
        for (int j = 0; j < 8; j++)
            if (lane < 9)
                g[j] = __ldg(&gen[(size_t)items[j] * 9 + lane]);

        #pragma unroll
        for (int j = 0; j < 8; j++) {
            float2* o = out + (size_t)(r0 + j) * 73;   // 8B-aligned rows
            __stcs(&o[lane * 2 + 0], make_float2(e[j].x, e[j].y));
            __stcs(&o[lane * 2 + 1], make_float2(e[j].z, e[j].w));
            if (lane < 9)
                __stcs(&o[64 + lane], g[j]);
        }
    } else {
        // Tail fallback (unused for B = 1M): one row at a time.
        for (int r = r0; r < B && r < r0 + ROWS_PER_WARP; r++) {
            int item = idx[r];
            float4 e = __ldg(&emb[(size_t)item * 32 + lane]);
            float2* o = out + (size_t)r * 73;
            o[lane * 2 + 0] = make_float2(e.x, e.y);
            o[lane * 2 + 1] = make_float2(e.z, e.w);
            if (lane < 9)
                o[64 + lane] = __ldg(&gen[(size_t)item * 9 + lane]);
        }
    }
}

extern "C" void kernel_launch(void* const* d_in, const int* in_sizes, int n_in,
                              void* d_out, int out_size)
{
    const int*    idx = (const int*)   d_in[0];
    const float4* emb = (const float4*)d_in[1];
    const float2* gen = (const float2*)d_in[2];
    float2*       out = (float2*)d_out;

    int B = in_sizes[0];                                   // 1048576
    int rowsPerBlock = 8 * ROWS_PER_WARP;                  // 8 warps/block
    int blocks = (B + rowsPerBlock - 1) / rowsPerBlock;    // 16384

    item_gather_concat_kernel<<<blocks, 256>>>(idx, emb, gen, out, B);
}